// round 1
// baseline (speedup 1.0000x reference)
#include <cuda_runtime.h>
#include <math.h>

// Problem constants (fixed shapes)
//   encoding: [32, 512, 1024] f32   (d_in[0])
//   W:        [256, 256] f32        (d_in[1])
//   b:        [256] f32             (d_in[2])
//   out:      [32, 32, 4, 256] f32
//
// Reduction: DCT/band/IDCT along batch collapses to mask(l,n) * enc (M@C = I,
// mask independent of k). Only l < 32 is kept. So:
//   out[r, o] = tanh(scale(r) * dot(enc_row_r, W[o,:]) + bias[o])
// with r = b*128 + l*4 + n  (b<32, l<32, n<4), enc_row = r + 1920*(r>>7).
// scale: n==0 -> 1 ; n==1 -> (l<16 ? 0.1 : 1) ; n>=2 -> 0.1

#define BM 32
#define BN 64
#define BK 32
#define KTOT 256
#define NTILES (KTOT / BK)

__device__ __forceinline__ float tanh_fast(float x) {
    // tanh(x) = 1 - 2/(exp(2x)+1); EX2+RCP MUFU path, ~1e-6 rel err, saturates
    // correctly at +/-1 for large |x|.
    float e = __expf(2.0f * x);
    return 1.0f - __fdividef(2.0f, e + 1.0f);
}

__global__ __launch_bounds__(256) void spectral_gemm_kernel(
    const float* __restrict__ enc,
    const float* __restrict__ W,
    const float* __restrict__ bias,
    float* __restrict__ out)
{
    __shared__ float As[BK][BM + 1];                   // pitch 33: conflict-free transposed stores
    __shared__ __align__(16) float Bs[BK][BN + 4];     // pitch 68: rows 16B-aligned for LDS.128

    const int tid = threadIdx.x;
    const int tx = tid & 15;   // N direction, 0..15 (covers 4 cols each)
    const int ty = tid >> 4;   // M direction, 0..15 (covers 2 rows each)
    const int bx = blockIdx.x; // row tile, 0..127
    const int by = blockIdx.y; // col tile, 0..3

    // A-load mapping: one float4 per thread per k-tile
    const int a_row = tid >> 3;            // 0..31 (local row)
    const int a_c4  = tid & 7;             // 0..7  (float4 within 32-wide k chunk)
    const int r_a   = bx * BM + a_row;     // global GEMM row
    const int b_a   = r_a >> 7;            // batch index
    const int enc_row = r_a + 1920 * b_a;  // row in encoding, units of 256 floats

    const float4* __restrict__ encv = (const float4*)enc;
    const float4* __restrict__ Wv   = (const float4*)W;

    float acc[2][4] = {};

    for (int kt = 0; kt < NTILES; ++kt) {
        // ---- load A tile (32 rows x 32 k), transpose into As[k][m]
        float4 av = encv[enc_row * 64 + kt * 8 + a_c4];
        As[a_c4 * 4 + 0][a_row] = av.x;
        As[a_c4 * 4 + 1][a_row] = av.y;
        As[a_c4 * 4 + 2][a_row] = av.z;
        As[a_c4 * 4 + 3][a_row] = av.w;

        // ---- load B tile (64 o-rows x 32 k), transpose into Bs[k][n]
        #pragma unroll
        for (int p = 0; p < 2; ++p) {
            int idx  = tid + p * 256;
            int brow = idx >> 3;           // 0..63 (local o)
            int c4   = idx & 7;
            float4 bv = Wv[(by * BN + brow) * 64 + kt * 8 + c4];
            Bs[c4 * 4 + 0][brow] = bv.x;
            Bs[c4 * 4 + 1][brow] = bv.y;
            Bs[c4 * 4 + 2][brow] = bv.z;
            Bs[c4 * 4 + 3][brow] = bv.w;
        }
        __syncthreads();

        // ---- compute: 2x4 register tile
        #pragma unroll
        for (int k = 0; k < BK; ++k) {
            float a0 = As[k][ty * 2 + 0];
            float a1 = As[k][ty * 2 + 1];
            float4 bq = *(const float4*)&Bs[k][tx * 4];
            acc[0][0] += a0 * bq.x;
            acc[0][1] += a0 * bq.y;
            acc[0][2] += a0 * bq.z;
            acc[0][3] += a0 * bq.w;
            acc[1][0] += a1 * bq.x;
            acc[1][1] += a1 * bq.y;
            acc[1][2] += a1 * bq.z;
            acc[1][3] += a1 * bq.w;
        }
        __syncthreads();
    }

    // ---- epilogue: per-row band scale, bias, tanh, store
    float4 bb = ((const float4*)bias)[by * 16 + tx];

    #pragma unroll
    for (int i = 0; i < 2; ++i) {
        int r = bx * BM + ty * 2 + i;
        int l = (r >> 2) & 31;
        int n = r & 3;
        float scale = (n == 0) ? 1.0f
                    : (n == 1) ? ((l < 16) ? 0.1f : 1.0f)
                    : 0.1f;
        float4 o;
        o.x = tanh_fast(fmaf(scale, acc[i][0], bb.x));
        o.y = tanh_fast(fmaf(scale, acc[i][1], bb.y));
        o.z = tanh_fast(fmaf(scale, acc[i][2], bb.z));
        o.w = tanh_fast(fmaf(scale, acc[i][3], bb.w));
        ((float4*)out)[r * 64 + by * 16 + tx] = o;
    }
}

extern "C" void kernel_launch(void* const* d_in, const int* in_sizes, int n_in,
                              void* d_out, int out_size) {
    const float* enc  = (const float*)d_in[0];
    const float* W    = (const float*)d_in[1];
    const float* bias = (const float*)d_in[2];
    float* out = (float*)d_out;

    dim3 grid(4096 / BM, 256 / BN);  // (128, 4)
    spectral_gemm_kernel<<<grid, 256>>>(enc, W, bias, out);
}

// round 2
// speedup vs baseline: 1.1313x; 1.1313x over previous
#include <cuda_runtime.h>

// Problem: out[r,o] = tanh(scale(r) * dot(enc_row(r), W[o,:]) + b[o])
//   r = b*128 + l*4 + n  (b<32, l<32, n<4)  -> M = 4096 rows
//   enc physical row = r + 1920*(r>>7)  (rows of 256 floats in [32,512,4,256])
//   o < 256, K = 256.
// (DCT/band/IDCT over batch collapses: idct(mask*dct(x)) = mask*x since the
//  band mask is independent of the DCT index.)
//
// GEMM config: BM=64, BN=64, BK=32, 256 threads, 4x4 thread tile computed as
// 2 packed-f32x2 M-pairs x 4 N-columns via fma.rn.f32x2 (Blackwell FFMA2).
//   A smem: [BK][64] f32, XOR-swizzled at float4 granularity -> LDS.128 bcast
//   B smem: [BK][128] f32,每 value DUPLICATED (b,b) + XOR swizzle -> LDS.64
//           delivers the packed scalar operand with no pack MOVs.
// Double-buffered smem, register-staged LDGs, one __syncthreads per k-tile.

#define BM 64
#define BN 64
#define BK 32
#define THREADS 256
#define KTILES 8   // K=256 / BK

__device__ __forceinline__ float tanh_fast(float x) {
    // tanh(x) = 1 - 2/(exp(2x)+1): EX2 + RCP MUFU path, ~1e-6 rel err,
    // saturates correctly at +/-1.
    float e = __expf(2.0f * x);
    return 1.0f - __fdividef(2.0f, e + 1.0f);
}

__device__ __forceinline__ unsigned long long pack2(float x, float y) {
    unsigned long long r;
    asm("mov.b64 %0, {%1, %2};" : "=l"(r) : "f"(x), "f"(y));
    return r;
}

__device__ __forceinline__ void ffma2(float2& d, unsigned long long a,
                                      unsigned long long b) {
    asm("fma.rn.f32x2 %0, %1, %2, %0;"
        : "+l"(reinterpret_cast<unsigned long long&>(d))
        : "l"(a), "l"(b));
}

__global__ __launch_bounds__(THREADS) void spectral_gemm_kernel(
    const float* __restrict__ enc,
    const float* __restrict__ W,
    const float* __restrict__ bias,
    float* __restrict__ out)
{
    // 16KB A + 32KB B(dup) = 48KB static smem (exactly at the static limit)
    __shared__ __align__(16) float As[2][BK * BM];     // [k][m], swizzled
    __shared__ __align__(16) float Bd[2][BK * 2 * BN]; // [k][2n], dup+swizzled

    const int tid = threadIdx.x;
    const int tx  = tid & 15;   // N group: columns tx + 16c, c=0..3
    const int ty  = tid >> 4;   // M group: rows 4ty .. 4ty+3
    const int bx  = blockIdx.x; // 0..63
    const int by  = blockIdx.y; // 0..3

    // global-load mapping: each thread moves 2 float4 of A and 2 of B per tile
    const int lr  = tid >> 3;   // 0..31: local row (and +32 for p=1)
    const int lc4 = tid & 7;    // 0..7 : float4 index within 32-wide k chunk

    const float4* __restrict__ encv = (const float4*)enc;
    const float4* __restrict__ Wv   = (const float4*)W;

    int encRow[2], wRow[2];
    #pragma unroll
    for (int p = 0; p < 2; ++p) {
        int rg = bx * BM + lr + p * 32;
        encRow[p] = rg + 1920 * (rg >> 7);
        wRow[p]   = by * BN + lr + p * 32;
    }

    float4 rA[2], rB[2];

    // ---- prologue: fetch tile 0, stage to smem buffer 0
    #pragma unroll
    for (int p = 0; p < 2; ++p) {
        rA[p] = encv[encRow[p] * 64 + lc4];
        rB[p] = Wv[wRow[p] * 64 + lc4];
    }
    #pragma unroll
    for (int p = 0; p < 2; ++p) {
        int r  = lr + p * 32;
        int R4 = r >> 2, Rw = r & 3;
        float va[4] = {rA[p].x, rA[p].y, rA[p].z, rA[p].w};
        float vb[4] = {rB[p].x, rB[p].y, rB[p].z, rB[p].w};
        #pragma unroll
        for (int j = 0; j < 4; ++j) {
            int k = lc4 * 4 + j;
            As[0][k * 64 + ((R4 ^ (k & 15)) << 2) + Rw] = va[j];
            int bi = k * 128 + 2 * (r ^ (k & 15));
            Bd[0][bi]     = vb[j];
            Bd[0][bi + 1] = vb[j];
        }
    }
    __syncthreads();

    float2 acc[2][4];
    #pragma unroll
    for (int i = 0; i < 2; ++i)
        #pragma unroll
        for (int c = 0; c < 4; ++c)
            acc[i][c] = make_float2(0.f, 0.f);

    for (int kt = 0; kt < KTILES; ++kt) {
        const int cur = kt & 1;

        // prefetch next tile into registers (latency hidden by compute)
        if (kt < KTILES - 1) {
            #pragma unroll
            for (int p = 0; p < 2; ++p) {
                rA[p] = encv[encRow[p] * 64 + (kt + 1) * 8 + lc4];
                rB[p] = Wv[wRow[p] * 64 + (kt + 1) * 8 + lc4];
            }
        }

        // ---- compute current tile: 8 FFMA2 per k
        const float4* Af = (const float4*)As[cur];
        const float*  Bf = Bd[cur];
        #pragma unroll
        for (int k = 0; k < BK; ++k) {
            float4 a = Af[k * 16 + (ty ^ (k & 15))];
            unsigned long long a01 = pack2(a.x, a.y);
            unsigned long long a23 = pack2(a.z, a.w);
            const float* brow = Bf + k * 128;
            #pragma unroll
            for (int c = 0; c < 4; ++c) {
                unsigned long long bb =
                    *(const unsigned long long*)(brow + 2 * ((tx + 16 * c) ^ (k & 15)));
                ffma2(acc[0][c], a01, bb);
                ffma2(acc[1][c], a23, bb);
            }
        }

        // ---- stage next tile to the other buffer
        if (kt < KTILES - 1) {
            const int nxt = cur ^ 1;
            #pragma unroll
            for (int p = 0; p < 2; ++p) {
                int r  = lr + p * 32;
                int R4 = r >> 2, Rw = r & 3;
                float va[4] = {rA[p].x, rA[p].y, rA[p].z, rA[p].w};
                float vb[4] = {rB[p].x, rB[p].y, rB[p].z, rB[p].w};
                #pragma unroll
                for (int j = 0; j < 4; ++j) {
                    int k = lc4 * 4 + j;
                    As[nxt][k * 64 + ((R4 ^ (k & 15)) << 2) + Rw] = va[j];
                    int bi = k * 128 + 2 * (r ^ (k & 15));
                    Bd[nxt][bi]     = vb[j];
                    Bd[nxt][bi + 1] = vb[j];
                }
            }
            __syncthreads();
        }
    }

    // ---- epilogue: per-row band scale, bias, tanh, store
    float bcol[4];
    #pragma unroll
    for (int c = 0; c < 4; ++c)
        bcol[c] = bias[by * 64 + tx + 16 * c];

    #pragma unroll
    for (int i = 0; i < 2; ++i) {
        #pragma unroll
        for (int h = 0; h < 2; ++h) {
            int r = bx * BM + ty * 4 + i * 2 + h;
            int l = (r >> 2) & 31;
            int n = r & 3;
            float scale = (n == 0) ? 1.0f
                        : (n == 1) ? ((l < 16) ? 0.1f : 1.0f)
                        : 0.1f;
            #pragma unroll
            for (int c = 0; c < 4; ++c) {
                float v = h ? acc[i][c].y : acc[i][c].x;
                out[r * 256 + by * 64 + tx + 16 * c] =
                    tanh_fast(fmaf(scale, v, bcol[c]));
            }
        }
    }
}

extern "C" void kernel_launch(void* const* d_in, const int* in_sizes, int n_in,
                              void* d_out, int out_size) {
    const float* enc  = (const float*)d_in[0];
    const float* W    = (const float*)d_in[1];
    const float* bias = (const float*)d_in[2];
    float* out = (float*)d_out;

    dim3 grid(4096 / BM, 256 / BN);  // (64, 4) = 256 blocks
    spectral_gemm_kernel<<<grid, THREADS>>>(enc, W, bias, out);
}